// round 1
// baseline (speedup 1.0000x reference)
#include <cuda_runtime.h>
#include <cuda_bf16.h>

// DynamicShortConvolution on GB300
// Stage 1: h = silu(x @ w1^T)                  [8192, 2048]  (scratch in g_h)
// Stage 2: flat = h @ w2^T + b2 ; kernels = flat.reshape(.., D, 4)
//          y[b,t,d] = sum_w xp[b, t-3+w, d] * kernels[b,t,d,w] ; out = silu(y)
// Stage 2's conv is fused into the GEMM epilogue: the 4 taps of channel d are
// columns 4d..4d+3 of flat, which live in the same thread's accumulator strip.

#define BM 128
#define BN 128
#define BK 16

#define M_ROWS 8192   // B*T
#define D_HID  2048
#define DG_HID 2048
#define KW_COLS 8192  // D*W
#define T_LEN  4096

// 64 MB scratch for h (static device array: allocation-guard safe)
__device__ float g_h[(size_t)M_ROWS * DG_HID];

__device__ __forceinline__ float silu_f(float v) {
    return v / (1.0f + __expf(-v));
}

// ---------------------------------------------------------------------------
// GEMM1: g_h[m,n] = silu( sum_k x[m,k] * w1[n,k] )    (NT gemm, K contiguous)
// ---------------------------------------------------------------------------
__global__ __launch_bounds__(256, 2)
void gemm1_silu_kernel(const float* __restrict__ A,   // x   [M, K]
                       const float* __restrict__ B)   // w1  [N, K]
{
    const int K = D_HID;
    const int N = DG_HID;
    __shared__ float As[BK][BM];
    __shared__ float Bs[BK][BN];

    const int bm = blockIdx.y * BM;
    const int bn = blockIdx.x * BN;
    const int tid = (int)threadIdx.x;
    const int tn = tid & 15;
    const int tm = tid >> 4;
    const int mBase = tm * 8;
    const int nBase = tn * 8;

    float acc[8][8];
    #pragma unroll
    for (int i = 0; i < 8; i++)
        #pragma unroll
        for (int j = 0; j < 8; j++) acc[i][j] = 0.f;

    for (int k0 = 0; k0 < K; k0 += BK) {
        #pragma unroll
        for (int s = 0; s < 2; s++) {
            int slot = tid + s * 256;          // 0..511
            int row  = slot >> 2;              // 0..127
            int kc   = (slot & 3) * 4;         // 0,4,8,12
            float4 va = *(const float4*)(A + (size_t)(bm + row) * K + k0 + kc);
            As[kc + 0][row] = va.x; As[kc + 1][row] = va.y;
            As[kc + 2][row] = va.z; As[kc + 3][row] = va.w;
            float4 vb = *(const float4*)(B + (size_t)(bn + row) * K + k0 + kc);
            Bs[kc + 0][row] = vb.x; Bs[kc + 1][row] = vb.y;
            Bs[kc + 2][row] = vb.z; Bs[kc + 3][row] = vb.w;
        }
        __syncthreads();
        #pragma unroll
        for (int kk = 0; kk < BK; kk++) {
            float a[8], b[8];
            *(float4*)&a[0] = *(const float4*)&As[kk][mBase];
            *(float4*)&a[4] = *(const float4*)&As[kk][mBase + 4];
            *(float4*)&b[0] = *(const float4*)&Bs[kk][nBase];
            *(float4*)&b[4] = *(const float4*)&Bs[kk][nBase + 4];
            #pragma unroll
            for (int i = 0; i < 8; i++)
                #pragma unroll
                for (int j = 0; j < 8; j++)
                    acc[i][j] += a[i] * b[j];
        }
        __syncthreads();
    }

    #pragma unroll
    for (int i = 0; i < 8; i++) {
        float* crow = g_h + (size_t)(bm + mBase + i) * N + bn + nBase;
        float4 v0, v1;
        v0.x = silu_f(acc[i][0]); v0.y = silu_f(acc[i][1]);
        v0.z = silu_f(acc[i][2]); v0.w = silu_f(acc[i][3]);
        v1.x = silu_f(acc[i][4]); v1.y = silu_f(acc[i][5]);
        v1.z = silu_f(acc[i][6]); v1.w = silu_f(acc[i][7]);
        *(float4*)(crow)     = v0;
        *(float4*)(crow + 4) = v1;
    }
}

// ---------------------------------------------------------------------------
// GEMM2 + conv: acc[m, j] = sum_g h[m,g] * w2[j,g]; then per channel d = j/4:
//   y = sum_w x[b, t-3+w, d] * (acc[m, 4d+w] + b2[4d+w]);  out = silu(y)
// ---------------------------------------------------------------------------
__global__ __launch_bounds__(256, 2)
void gemm2_conv_kernel(const float* __restrict__ B,   // w2 [N=8192, K=2048]
                       const float* __restrict__ b2,  // [8192]
                       const float* __restrict__ x,   // [2, 4096, 2048]
                       float* __restrict__ out)       // [2, 4096, 2048]
{
    const int K = DG_HID;
    __shared__ float As[BK][BM];
    __shared__ float Bs[BK][BN];

    const int bm = blockIdx.y * BM;
    const int bn = blockIdx.x * BN;
    const int tid = (int)threadIdx.x;
    const int tn = tid & 15;
    const int tm = tid >> 4;
    const int mBase = tm * 8;
    const int nBase = tn * 8;

    const float* A = g_h;

    float acc[8][8];
    #pragma unroll
    for (int i = 0; i < 8; i++)
        #pragma unroll
        for (int j = 0; j < 8; j++) acc[i][j] = 0.f;

    for (int k0 = 0; k0 < K; k0 += BK) {
        #pragma unroll
        for (int s = 0; s < 2; s++) {
            int slot = tid + s * 256;
            int row  = slot >> 2;
            int kc   = (slot & 3) * 4;
            float4 va = *(const float4*)(A + (size_t)(bm + row) * K + k0 + kc);
            As[kc + 0][row] = va.x; As[kc + 1][row] = va.y;
            As[kc + 2][row] = va.z; As[kc + 3][row] = va.w;
            float4 vb = *(const float4*)(B + (size_t)(bn + row) * K + k0 + kc);
            Bs[kc + 0][row] = vb.x; Bs[kc + 1][row] = vb.y;
            Bs[kc + 2][row] = vb.z; Bs[kc + 3][row] = vb.w;
        }
        __syncthreads();
        #pragma unroll
        for (int kk = 0; kk < BK; kk++) {
            float a[8], b[8];
            *(float4*)&a[0] = *(const float4*)&As[kk][mBase];
            *(float4*)&a[4] = *(const float4*)&As[kk][mBase + 4];
            *(float4*)&b[0] = *(const float4*)&Bs[kk][nBase];
            *(float4*)&b[4] = *(const float4*)&Bs[kk][nBase + 4];
            #pragma unroll
            for (int i = 0; i < 8; i++)
                #pragma unroll
                for (int j = 0; j < 8; j++)
                    acc[i][j] += a[i] * b[j];
        }
        __syncthreads();
    }

    // Fused epilogue: bias + causal depthwise dynamic conv + silu.
    // Per-thread column strip is 8 wide and 4-aligned -> exactly 2 channels.
    #pragma unroll
    for (int i = 0; i < 8; i++) {
        int m = bm + mBase + i;
        int b = m >> 12;         // / 4096
        int t = m & (T_LEN - 1);
        #pragma unroll
        for (int dg = 0; dg < 2; dg++) {
            int gcol = bn + nBase + dg * 4;  // first tap column
            int d = gcol >> 2;               // channel
            float y = 0.f;
            #pragma unroll
            for (int w = 0; w < 4; w++) {
                float kv = acc[i][dg * 4 + w] + b2[gcol + w];
                int ts = t - 3 + w;
                float xv = (ts >= 0)
                    ? x[((size_t)b * T_LEN + ts) * D_HID + d] : 0.f;
                y += xv * kv;
            }
            out[((size_t)b * T_LEN + t) * D_HID + d] = silu_f(y);
        }
    }
}

extern "C" void kernel_launch(void* const* d_in, const int* in_sizes, int n_in,
                              void* d_out, int out_size) {
    const float* x  = (const float*)d_in[0];   // [2,4096,2048]
    const float* w1 = (const float*)d_in[1];   // [2048,2048]
    const float* w2 = (const float*)d_in[2];   // [8192,2048]
    const float* b2 = (const float*)d_in[3];   // [8192]
    float* out = (float*)d_out;

    dim3 blk(256);
    dim3 g1(DG_HID / BN, M_ROWS / BM);    // (16, 64)
    gemm1_silu_kernel<<<g1, blk>>>(x, w1);

    dim3 g2(KW_COLS / BN, M_ROWS / BM);   // (64, 64)
    gemm2_conv_kernel<<<g2, blk>>>(w2, b2, x, out);
}

// round 3
// speedup vs baseline: 2.8069x; 2.8069x over previous
#include <cuda_runtime.h>
#include <cuda_bf16.h>
#include <cstdint>
#include <cstddef>

typedef __nv_bfloat16 bf16;

#define D_HID 2048
#define T_LEN 4096
#define M_ROWS 8192
#define KW 8192

// ---------------- scratch (static device arrays: allocation-guard safe) ----
__device__ __align__(256) bf16 g_xhi[(size_t)M_ROWS * D_HID];
__device__ __align__(256) bf16 g_xlo[(size_t)M_ROWS * D_HID];
__device__ __align__(256) bf16 g_w1hi[(size_t)D_HID * D_HID];
__device__ __align__(256) bf16 g_w1lo[(size_t)D_HID * D_HID];
__device__ __align__(256) bf16 g_w2hi[(size_t)KW * D_HID];
__device__ __align__(256) bf16 g_w2lo[(size_t)KW * D_HID];
__device__ __align__(256) bf16 g_hhi[(size_t)M_ROWS * D_HID];
__device__ __align__(256) bf16 g_hlo[(size_t)M_ROWS * D_HID];

// ---------------- helpers ---------------------------------------------------
__device__ __forceinline__ uint32_t smem_u32(const void* p) {
    uint32_t a;
    asm("{ .reg .u64 t; cvta.to.shared.u64 t, %1; cvt.u32.u64 %0, t; }"
        : "=r"(a) : "l"(p));
    return a;
}
__device__ __forceinline__ void cp16(uint32_t dst, const void* src) {
    asm volatile("cp.async.cg.shared.global [%0], [%1], 16;" :: "r"(dst), "l"(src));
}
#define CP_COMMIT() asm volatile("cp.async.commit_group;" ::: "memory")
#define CP_WAIT2()  asm volatile("cp.async.wait_group 2;" ::: "memory")

__device__ __forceinline__ void ldsm4(uint32_t r[4], uint32_t addr) {
    asm volatile("ldmatrix.sync.aligned.m8n8.x4.shared.b16 {%0,%1,%2,%3}, [%4];"
        : "=r"(r[0]), "=r"(r[1]), "=r"(r[2]), "=r"(r[3]) : "r"(addr));
}
__device__ __forceinline__ void mma_bf16(float c[4], const uint32_t a[4],
                                         uint32_t b0, uint32_t b1) {
    asm volatile("mma.sync.aligned.m16n8k16.row.col.f32.bf16.bf16.f32 "
        "{%0,%1,%2,%3}, {%4,%5,%6,%7}, {%8,%9}, {%0,%1,%2,%3};"
        : "+f"(c[0]), "+f"(c[1]), "+f"(c[2]), "+f"(c[3])
        : "r"(a[0]), "r"(a[1]), "r"(a[2]), "r"(a[3]), "r"(b0), "r"(b1));
}
__device__ __forceinline__ float silu_f(float v) { return v / (1.0f + __expf(-v)); }

// swizzled byte offset within a [128 rows][32 cols bf16] tile (64B rows)
__device__ __forceinline__ uint32_t sw_off(int row, int c16) {
    return (uint32_t)(row * 64 + ((c16 ^ ((row >> 1) & 3)) << 4));
}

// ---------------- split: fp32 -> bf16 hi/lo --------------------------------
__global__ void split_kernel(const float* __restrict__ in, bf16* __restrict__ hi,
                             bf16* __restrict__ lo, int n4) {
    int i = blockIdx.x * blockDim.x + threadIdx.x;
    if (i >= n4) return;
    float4 v = ((const float4*)in)[i];
    bf16 h0 = __float2bfloat16_rn(v.x), h1 = __float2bfloat16_rn(v.y);
    bf16 h2 = __float2bfloat16_rn(v.z), h3 = __float2bfloat16_rn(v.w);
    __nv_bfloat162 hp0, hp1, lp0, lp1;
    hp0.x = h0; hp0.y = h1; hp1.x = h2; hp1.y = h3;
    lp0.x = __float2bfloat16_rn(v.x - __bfloat162float(h0));
    lp0.y = __float2bfloat16_rn(v.y - __bfloat162float(h1));
    lp1.x = __float2bfloat16_rn(v.z - __bfloat162float(h2));
    lp1.y = __float2bfloat16_rn(v.w - __bfloat162float(h3));
    ((__nv_bfloat162*)hi)[2 * i] = hp0; ((__nv_bfloat162*)hi)[2 * i + 1] = hp1;
    ((__nv_bfloat162*)lo)[2 * i] = lp0; ((__nv_bfloat162*)lo)[2 * i + 1] = lp1;
}

// ---------------- main mma.sync GEMM (3xBF16 split) -------------------------
// stage: Ahi[128][32] +0, Alo +8192, Bhi +16384, Blo +24576 (32 KB / stage)
#define STAGE_B 32768u
#define SMEM_BYTES (3 * 32768)   // 98304; epilogue reuses this region

__device__ __forceinline__ void load_stage(uint32_t sbase,
    const bf16* Ahi, const bf16* Alo, const bf16* Bhi, const bf16* Blo,
    int k0, int tid) {
    const bf16* srcs[4] = {Ahi, Alo, Bhi, Blo};
    #pragma unroll
    for (int t = 0; t < 4; t++) {
        uint32_t tb = sbase + (uint32_t)t * 8192u;
        #pragma unroll
        for (int i = 0; i < 2; i++) {
            int id = tid + i * 256;
            int row = id >> 2, c16 = id & 3;
            cp16(tb + sw_off(row, c16), srcs[t] + (size_t)row * D_HID + k0 + c16 * 8);
        }
    }
}

template<int MODE>
__global__ void __launch_bounds__(256, 2)
gemm3x_kernel(const float* __restrict__ xin, const float* __restrict__ b2,
              float* __restrict__ out) {
    extern __shared__ char smem[];
    uint32_t sb = smem_u32(smem);
    const int tid = threadIdx.x;
    const int l   = tid & 31;
    const int wid = tid >> 5;
    const int wm  = wid & 1;    // 2 M-warps (64 rows each)
    const int wn  = wid >> 1;   // 4 N-warps (32 cols each)
    const int bm = blockIdx.y * 128, bn = blockIdx.x * 128;

    const bf16* Ahi = (MODE == 0 ? g_xhi : g_hhi) + (size_t)bm * D_HID;
    const bf16* Alo = (MODE == 0 ? g_xlo : g_hlo) + (size_t)bm * D_HID;
    const bf16* Bhi = (MODE == 0 ? g_w1hi : g_w2hi) + (size_t)bn * D_HID;
    const bf16* Blo = (MODE == 0 ? g_w1lo : g_w2lo) + (size_t)bn * D_HID;

    float acc[4][4][4];
    #pragma unroll
    for (int a = 0; a < 4; a++)
        #pragma unroll
        for (int b = 0; b < 4; b++)
            #pragma unroll
            for (int c = 0; c < 4; c++) acc[a][b][c] = 0.f;

    load_stage(sb + 0 * STAGE_B, Ahi, Alo, Bhi, Blo, 0, tid);  CP_COMMIT();
    load_stage(sb + 1 * STAGE_B, Ahi, Alo, Bhi, Blo, 32, tid); CP_COMMIT();
    load_stage(sb + 2 * STAGE_B, Ahi, Alo, Bhi, Blo, 64, tid); CP_COMMIT();

    const int NIT = D_HID / 32;   // 64
    int s = 0;
    for (int it = 0; it < NIT; it++) {
        CP_WAIT2();
        __syncthreads();
        uint32_t sbase = sb + (uint32_t)s * STAGE_B;
        #pragma unroll
        for (int ks = 0; ks < 2; ks++) {
            uint32_t ah[4][4], al[4][4];
            #pragma unroll
            for (int mt = 0; mt < 4; mt++) {
                int row = wm * 64 + mt * 16 + (l & 15);
                uint32_t off = sw_off(row, ks * 2 + (l >> 4));
                ldsm4(ah[mt], sbase + off);
                ldsm4(al[mt], sbase + 8192u + off);
            }
            #pragma unroll
            for (int blk = 0; blk < 2; blk++) {
                int row = wn * 32 + blk * 16 + (l & 15);
                uint32_t off = sw_off(row, ks * 2 + (l >> 4));
                uint32_t bh[4], bl[4];
                ldsm4(bh, sbase + 16384u + off);
                ldsm4(bl, sbase + 24576u + off);
                #pragma unroll
                for (int mt = 0; mt < 4; mt++) {
                    #pragma unroll
                    for (int sub = 0; sub < 2; sub++) {
                        float* C = acc[mt][blk * 2 + sub];
                        mma_bf16(C, ah[mt], bh[sub], bh[sub + 2]);
                        mma_bf16(C, al[mt], bh[sub], bh[sub + 2]);
                        mma_bf16(C, ah[mt], bl[sub], bl[sub + 2]);
                    }
                }
            }
        }
        __syncthreads();
        if (it + 3 < NIT)
            load_stage(sbase, Ahi, Alo, Bhi, Blo, (it + 3) * 32, tid);
        CP_COMMIT();
        s = (s == 2) ? 0 : s + 1;
    }
    __syncthreads();   // pipeline smem now reusable for epilogue

    if (MODE == 0) {
        // silu + bf16 split of h, staged for coalesced global stores
        uint32_t* hi_buf = (uint32_t*)smem;            // [128][66]
        uint32_t* lo_buf = hi_buf + 128 * 66;
        #pragma unroll
        for (int mt = 0; mt < 4; mt++) {
            #pragma unroll
            for (int nt = 0; nt < 4; nt++) {
                int r0 = wm * 64 + mt * 16 + (l >> 2);
                int cu = wn * 16 + nt * 4 + (l & 3);
                #pragma unroll
                for (int half = 0; half < 2; half++) {
                    int r = r0 + half * 8;
                    float v0 = silu_f(acc[mt][nt][half * 2 + 0]);
                    float v1 = silu_f(acc[mt][nt][half * 2 + 1]);
                    bf16 h0 = __float2bfloat16_rn(v0), h1 = __float2bfloat16_rn(v1);
                    __nv_bfloat162 hp, lp;
                    hp.x = h0; hp.y = h1;
                    lp.x = __float2bfloat16_rn(v0 - __bfloat162float(h0));
                    lp.y = __float2bfloat16_rn(v1 - __bfloat162float(h1));
                    hi_buf[r * 66 + cu] = *(uint32_t*)&hp;
                    lo_buf[r * 66 + cu] = *(uint32_t*)&lp;
                }
            }
        }
        __syncthreads();
        for (int idx = tid; idx < 128 * 64; idx += 256) {
            int r = idx >> 6, c = idx & 63;
            ((uint32_t*)(g_hhi + (size_t)(bm + r) * D_HID + bn))[c] = hi_buf[r * 66 + c];
            ((uint32_t*)(g_hlo + (size_t)(bm + r) * D_HID + bn))[c] = lo_buf[r * 66 + c];
        }
    } else {
        // bias + causal 4-tap dynamic conv + silu
        float* ksm = (float*)smem;                  // [4][128][33]
        float* xs  = (float*)(smem + 67584);        // [131][33]
        float* b2s = (float*)(smem + 67584 + 17292 + 4);  // [128]
        const int b  = bm >> 12;
        const int t0 = bm & (T_LEN - 1);
        const int d0 = bn >> 2;
        for (int idx = tid; idx < 131 * 32; idx += 256) {
            int r = idx >> 5, c = idx & 31;
            int t = t0 - 3 + r;
            float v = 0.f;
            if (t >= 0) v = xin[((size_t)b * T_LEN + t) * D_HID + d0 + c];
            xs[r * 33 + c] = v;
        }
        if (tid < 128) b2s[tid] = b2[bn + tid];
        __syncthreads();
        #pragma unroll
        for (int mt = 0; mt < 4; mt++) {
            #pragma unroll
            for (int nt = 0; nt < 4; nt++) {
                int r0   = wm * 64 + mt * 16 + (l >> 2);
                int col0 = wn * 32 + nt * 8 + (l & 3) * 2;
                #pragma unroll
                for (int cc = 0; cc < 4; cc++) {
                    int r   = r0 + ((cc >> 1) << 3);
                    int col = col0 + (cc & 1);
                    float val = acc[mt][nt][cc] + b2s[col];
                    ksm[(((col & 3) * 128) + r) * 33 + (col >> 2)] = val;
                }
            }
        }
        __syncthreads();
        {
            int c = tid & 31, rg = tid >> 5;
            #pragma unroll
            for (int i = 0; i < 16; i++) {
                int r = rg * 16 + i;
                float y = 0.f;
                #pragma unroll
                for (int w = 0; w < 4; w++)
                    y += xs[(r + w) * 33 + c] * ksm[((w * 128) + r) * 33 + c];
                out[(size_t)(bm + r) * D_HID + d0 + c] = silu_f(y);
            }
        }
    }
}

// ---------------- launch ----------------------------------------------------
extern "C" void kernel_launch(void* const* d_in, const int* in_sizes, int n_in,
                              void* d_out, int out_size) {
    const float* x  = (const float*)d_in[0];   // [2,4096,2048]
    const float* w1 = (const float*)d_in[1];   // [2048,2048]
    const float* w2 = (const float*)d_in[2];   // [8192,2048]
    const float* b2 = (const float*)d_in[3];   // [8192]
    float* out = (float*)d_out;

    cudaFuncSetAttribute(gemm3x_kernel<0>, cudaFuncAttributeMaxDynamicSharedMemorySize, SMEM_BYTES);
    cudaFuncSetAttribute(gemm3x_kernel<1>, cudaFuncAttributeMaxDynamicSharedMemorySize, SMEM_BYTES);

    void *pxh, *pxl, *pw1h, *pw1l, *pw2h, *pw2l;
    cudaGetSymbolAddress(&pxh, g_xhi);  cudaGetSymbolAddress(&pxl, g_xlo);
    cudaGetSymbolAddress(&pw1h, g_w1hi); cudaGetSymbolAddress(&pw1l, g_w1lo);
    cudaGetSymbolAddress(&pw2h, g_w2hi); cudaGetSymbolAddress(&pw2l, g_w2lo);

    {
        int n4 = M_ROWS * D_HID / 4;
        split_kernel<<<(n4 + 255) / 256, 256>>>(x, (bf16*)pxh, (bf16*)pxl, n4);
    }
    {
        int n4 = D_HID * D_HID / 4;
        split_kernel<<<(n4 + 255) / 256, 256>>>(w1, (bf16*)pw1h, (bf16*)pw1l, n4);
    }
    {
        int n4 = KW * D_HID / 4;
        split_kernel<<<(n4 + 255) / 256, 256>>>(w2, (bf16*)pw2h, (bf16*)pw2l, n4);
    }

    dim3 g1(D_HID / 128, M_ROWS / 128);   // (16, 64)
    gemm3x_kernel<0><<<g1, 256, SMEM_BYTES>>>(x, b2, out);

    dim3 g2(KW / 128, M_ROWS / 128);      // (64, 64)
    gemm3x_kernel<1><<<g2, 256, SMEM_BYTES>>>(x, b2, out);
}

// round 4
// speedup vs baseline: 2.9887x; 1.0648x over previous
#include <cuda_runtime.h>
#include <cuda_bf16.h>
#include <cstdint>
#include <cstddef>

typedef __nv_bfloat16 bf16;

#define D_HID 2048
#define T_LEN 4096
#define M_ROWS 8192
#define KW 8192

// ---------------- scratch (static device arrays: allocation-guard safe) ----
__device__ __align__(256) bf16 g_xhi[(size_t)M_ROWS * D_HID];
__device__ __align__(256) bf16 g_xlo[(size_t)M_ROWS * D_HID];
__device__ __align__(256) bf16 g_w1hi[(size_t)D_HID * D_HID];
__device__ __align__(256) bf16 g_w1lo[(size_t)D_HID * D_HID];
__device__ __align__(256) bf16 g_w2hi[(size_t)KW * D_HID];
__device__ __align__(256) bf16 g_w2lo[(size_t)KW * D_HID];
__device__ __align__(256) bf16 g_hhi[(size_t)M_ROWS * D_HID];
__device__ __align__(256) bf16 g_hlo[(size_t)M_ROWS * D_HID];

// ---------------- helpers ---------------------------------------------------
__device__ __forceinline__ uint32_t smem_u32(const void* p) {
    uint32_t a;
    asm("{ .reg .u64 t; cvta.to.shared.u64 t, %1; cvt.u32.u64 %0, t; }"
        : "=r"(a) : "l"(p));
    return a;
}
__device__ __forceinline__ void cp16(uint32_t dst, const void* src) {
    asm volatile("cp.async.cg.shared.global [%0], [%1], 16;" :: "r"(dst), "l"(src));
}
#define CP_COMMIT() asm volatile("cp.async.commit_group;" ::: "memory")
#define CP_WAIT1()  asm volatile("cp.async.wait_group 1;" ::: "memory")

__device__ __forceinline__ void ldsm4(uint32_t r[4], uint32_t addr) {
    asm volatile("ldmatrix.sync.aligned.m8n8.x4.shared.b16 {%0,%1,%2,%3}, [%4];"
        : "=r"(r[0]), "=r"(r[1]), "=r"(r[2]), "=r"(r[3]) : "r"(addr));
}
__device__ __forceinline__ void mma_bf16(float c[4], const uint32_t a[4],
                                         uint32_t b0, uint32_t b1) {
    asm volatile("mma.sync.aligned.m16n8k16.row.col.f32.bf16.bf16.f32 "
        "{%0,%1,%2,%3}, {%4,%5,%6,%7}, {%8,%9}, {%0,%1,%2,%3};"
        : "+f"(c[0]), "+f"(c[1]), "+f"(c[2]), "+f"(c[3])
        : "r"(a[0]), "r"(a[1]), "r"(a[2]), "r"(a[3]), "r"(b0), "r"(b1));
}
__device__ __forceinline__ float silu_f(float v) { return v / (1.0f + __expf(-v)); }

// swizzled byte offset within a [128 rows][32 cols bf16] tile (64B rows)
__device__ __forceinline__ uint32_t sw_off(int row, int c16) {
    return (uint32_t)(row * 64 + ((c16 ^ ((row >> 1) & 3)) << 4));
}

// ---------------- split: fp32 -> bf16 hi/lo --------------------------------
__global__ void split_kernel(const float* __restrict__ in, bf16* __restrict__ hi,
                             bf16* __restrict__ lo, int n4) {
    int i = blockIdx.x * blockDim.x + threadIdx.x;
    if (i >= n4) return;
    float4 v = ((const float4*)in)[i];
    bf16 h0 = __float2bfloat16_rn(v.x), h1 = __float2bfloat16_rn(v.y);
    bf16 h2 = __float2bfloat16_rn(v.z), h3 = __float2bfloat16_rn(v.w);
    __nv_bfloat162 hp0, hp1, lp0, lp1;
    hp0.x = h0; hp0.y = h1; hp1.x = h2; hp1.y = h3;
    lp0.x = __float2bfloat16_rn(v.x - __bfloat162float(h0));
    lp0.y = __float2bfloat16_rn(v.y - __bfloat162float(h1));
    lp1.x = __float2bfloat16_rn(v.z - __bfloat162float(h2));
    lp1.y = __float2bfloat16_rn(v.w - __bfloat162float(h3));
    ((__nv_bfloat162*)hi)[2 * i] = hp0; ((__nv_bfloat162*)hi)[2 * i + 1] = hp1;
    ((__nv_bfloat162*)lo)[2 * i] = lp0; ((__nv_bfloat162*)lo)[2 * i + 1] = lp1;
}

// ---------------- main mma.sync GEMM (3xBF16 split) -------------------------
// stage layout: Ahi[128][32] +0, Alo +8192, Bhi +16384, Blo +24576 (32 KB)
#define STAGE_B 32768u
#define SMEM_BYTES (3 * 32768)   // 98304; epilogue reuses this region

template<int MODE>
__global__ void __launch_bounds__(256, 2)
gemm3x_kernel(const float* __restrict__ xin, const float* __restrict__ b2,
              float* __restrict__ out) {
    extern __shared__ char smem[];
    uint32_t sb = smem_u32(smem);
    const int tid = threadIdx.x;
    const int l   = tid & 31;
    const int wid = tid >> 5;
    const int wm  = wid & 1;    // 2 M-warps (64 rows each)
    const int wn  = wid >> 1;   // 4 N-warps (32 cols each)
    const int bm = blockIdx.y * 128, bn = blockIdx.x * 128;

    const bf16* Ahi = (MODE == 0 ? g_xhi : g_hhi) + (size_t)bm * D_HID;
    const bf16* Alo = (MODE == 0 ? g_xlo : g_hlo) + (size_t)bm * D_HID;
    const bf16* Bhi = (MODE == 0 ? g_w1hi : g_w2hi) + (size_t)bn * D_HID;
    const bf16* Blo = (MODE == 0 ? g_w1lo : g_w2lo) + (size_t)bn * D_HID;

    // ---- hoisted cp.async addressing: each thread copies 2 rows per tile ----
    const int lrow = tid >> 2, lc16 = tid & 3;
    const uint32_t so0 = sw_off(lrow, lc16);            // slot0; slot1 = +4096
    const bf16* srcA0 = Ahi + (size_t)lrow * D_HID + lc16 * 8;
    const bf16* srcA1 = Alo + (size_t)lrow * D_HID + lc16 * 8;
    const bf16* srcB0 = Bhi + (size_t)lrow * D_HID + lc16 * 8;
    const bf16* srcB1 = Blo + (size_t)lrow * D_HID + lc16 * 8;
    const size_t R64 = (size_t)64 * D_HID;

    // ---- hoisted ldmatrix offsets (tile-relative) ----
    uint32_t offA[4][2], offB[2][2];
    #pragma unroll
    for (int mt = 0; mt < 4; mt++) {
        int row = wm * 64 + mt * 16 + (l & 15);
        #pragma unroll
        for (int ks = 0; ks < 2; ks++)
            offA[mt][ks] = sw_off(row, ks * 2 + (l >> 4));
    }
    #pragma unroll
    for (int blk = 0; blk < 2; blk++) {
        int row = wn * 32 + blk * 16 + (l & 15);
        #pragma unroll
        for (int ks = 0; ks < 2; ks++)
            offB[blk][ks] = sw_off(row, ks * 2 + (l >> 4));
    }

    float acc[4][4][4];
    #pragma unroll
    for (int a = 0; a < 4; a++)
        #pragma unroll
        for (int b = 0; b < 4; b++)
            #pragma unroll
            for (int c = 0; c < 4; c++) acc[a][b][c] = 0.f;

    uint32_t sb0 = sb, sb1 = sb + STAGE_B, sb2 = sb + 2 * STAGE_B;

    // one stage load = 8 cp16 per thread (4 tiles x 2 row-slots)
    #define DO_LOAD(base) do { \
        uint32_t _t = (base) + so0; \
        cp16(_t,              srcA0); cp16(_t + 4096,          srcA0 + R64); \
        cp16(_t + 8192,       srcA1); cp16(_t + 8192 + 4096,   srcA1 + R64); \
        cp16(_t + 16384,      srcB0); cp16(_t + 16384 + 4096,  srcB0 + R64); \
        cp16(_t + 24576,      srcB1); cp16(_t + 24576 + 4096,  srcB1 + R64); \
        srcA0 += 32; srcA1 += 32; srcB0 += 32; srcB1 += 32; \
    } while (0)

    DO_LOAD(sb0); CP_COMMIT();
    DO_LOAD(sb1); CP_COMMIT();

    const int NIT = D_HID / 32;   // 64
    for (int it = 0; it < NIT; it++) {
        CP_WAIT1();
        __syncthreads();
        // prefetch stage it+2 into the buffer consumed at it-1
        if (it < NIT - 2) DO_LOAD(sb2);
        CP_COMMIT();

        #pragma unroll
        for (int ks = 0; ks < 2; ks++) {
            uint32_t bh[2][4], bl[2][4];
            #pragma unroll
            for (int blk = 0; blk < 2; blk++) {
                ldsm4(bh[blk], sb0 + 16384u + offB[blk][ks]);
                ldsm4(bl[blk], sb0 + 24576u + offB[blk][ks]);
            }
            #pragma unroll
            for (int mt = 0; mt < 4; mt++) {
                uint32_t ah[4], al[4];
                ldsm4(ah, sb0 + offA[mt][ks]);
                ldsm4(al, sb0 + 8192u + offA[mt][ks]);
                #pragma unroll
                for (int blk = 0; blk < 2; blk++) {
                    #pragma unroll
                    for (int sub = 0; sub < 2; sub++) {
                        float* C = acc[mt][blk * 2 + sub];
                        mma_bf16(C, ah, bh[blk][sub], bh[blk][sub + 2]);
                        mma_bf16(C, al, bh[blk][sub], bh[blk][sub + 2]);
                        mma_bf16(C, ah, bl[blk][sub], bl[blk][sub + 2]);
                    }
                }
            }
        }
        // rotate stages
        uint32_t t = sb0; sb0 = sb1; sb1 = sb2; sb2 = t;
    }
    __syncthreads();   // pipeline smem now reusable for epilogue

    if (MODE == 0) {
        // silu + bf16 split of h, staged for coalesced global stores
        uint32_t* hi_buf = (uint32_t*)smem;            // [128][66]
        uint32_t* lo_buf = hi_buf + 128 * 66;
        #pragma unroll
        for (int mt = 0; mt < 4; mt++) {
            #pragma unroll
            for (int nt = 0; nt < 4; nt++) {
                int r0 = wm * 64 + mt * 16 + (l >> 2);
                int cu = wn * 16 + nt * 4 + (l & 3);
                #pragma unroll
                for (int half = 0; half < 2; half++) {
                    int r = r0 + half * 8;
                    float v0 = silu_f(acc[mt][nt][half * 2 + 0]);
                    float v1 = silu_f(acc[mt][nt][half * 2 + 1]);
                    bf16 h0 = __float2bfloat16_rn(v0), h1 = __float2bfloat16_rn(v1);
                    __nv_bfloat162 hp, lp;
                    hp.x = h0; hp.y = h1;
                    lp.x = __float2bfloat16_rn(v0 - __bfloat162float(h0));
                    lp.y = __float2bfloat16_rn(v1 - __bfloat162float(h1));
                    hi_buf[r * 66 + cu] = *(uint32_t*)&hp;
                    lo_buf[r * 66 + cu] = *(uint32_t*)&lp;
                }
            }
        }
        __syncthreads();
        for (int idx = tid; idx < 128 * 64; idx += 256) {
            int r = idx >> 6, c = idx & 63;
            ((uint32_t*)(g_hhi + (size_t)(bm + r) * D_HID + bn))[c] = hi_buf[r * 66 + c];
            ((uint32_t*)(g_hlo + (size_t)(bm + r) * D_HID + bn))[c] = lo_buf[r * 66 + c];
        }
    } else {
        // bias + causal 4-tap dynamic conv + silu
        float* ksm = (float*)smem;                  // [4][128][33]
        float* xs  = (float*)(smem + 67584);        // [131][33]
        float* b2s = (float*)(smem + 67584 + 17292 + 4);  // [128]
        const int b  = bm >> 12;
        const int t0 = bm & (T_LEN - 1);
        const int d0 = bn >> 2;
        for (int idx = tid; idx < 131 * 32; idx += 256) {
            int r = idx >> 5, c = idx & 31;
            int t = t0 - 3 + r;
            float v = 0.f;
            if (t >= 0) v = xin[((size_t)b * T_LEN + t) * D_HID + d0 + c];
            xs[r * 33 + c] = v;
        }
        if (tid < 128) b2s[tid] = b2[bn + tid];
        __syncthreads();
        #pragma unroll
        for (int mt = 0; mt < 4; mt++) {
            #pragma unroll
            for (int nt = 0; nt < 4; nt++) {
                int r0   = wm * 64 + mt * 16 + (l >> 2);
                int col0 = wn * 32 + nt * 8 + (l & 3) * 2;
                #pragma unroll
                for (int cc = 0; cc < 4; cc++) {
                    int r   = r0 + ((cc >> 1) << 3);
                    int col = col0 + (cc & 1);
                    float val = acc[mt][nt][cc] + b2s[col];
                    ksm[(((col & 3) * 128) + r) * 33 + (col >> 2)] = val;
                }
            }
        }
        __syncthreads();
        {
            int c = tid & 31, rg = tid >> 5;
            #pragma unroll
            for (int i = 0; i < 16; i++) {
                int r = rg * 16 + i;
                float y = 0.f;
                #pragma unroll
                for (int w = 0; w < 4; w++)
                    y += xs[(r + w) * 33 + c] * ksm[((w * 128) + r) * 33 + c];
                out[(size_t)(bm + r) * D_HID + d0 + c] = silu_f(y);
            }
        }
    }
}

// ---------------- launch ----------------------------------------------------
extern "C" void kernel_launch(void* const* d_in, const int* in_sizes, int n_in,
                              void* d_out, int out_size) {
    const float* x  = (const float*)d_in[0];   // [2,4096,2048]
    const float* w1 = (const float*)d_in[1];   // [2048,2048]
    const float* w2 = (const float*)d_in[2];   // [8192,2048]
    const float* b2 = (const float*)d_in[3];   // [8192]
    float* out = (float*)d_out;

    cudaFuncSetAttribute(gemm3x_kernel<0>, cudaFuncAttributeMaxDynamicSharedMemorySize, SMEM_BYTES);
    cudaFuncSetAttribute(gemm3x_kernel<1>, cudaFuncAttributeMaxDynamicSharedMemorySize, SMEM_BYTES);

    void *pxh, *pxl, *pw1h, *pw1l, *pw2h, *pw2l;
    cudaGetSymbolAddress(&pxh, g_xhi);  cudaGetSymbolAddress(&pxl, g_xlo);
    cudaGetSymbolAddress(&pw1h, g_w1hi); cudaGetSymbolAddress(&pw1l, g_w1lo);
    cudaGetSymbolAddress(&pw2h, g_w2hi); cudaGetSymbolAddress(&pw2l, g_w2lo);

    {
        int n4 = M_ROWS * D_HID / 4;
        split_kernel<<<(n4 + 255) / 256, 256>>>(x, (bf16*)pxh, (bf16*)pxl, n4);
    }
    {
        int n4 = D_HID * D_HID / 4;
        split_kernel<<<(n4 + 255) / 256, 256>>>(w1, (bf16*)pw1h, (bf16*)pw1l, n4);
    }
    {
        int n4 = KW * D_HID / 4;
        split_kernel<<<(n4 + 255) / 256, 256>>>(w2, (bf16*)pw2h, (bf16*)pw2l, n4);
    }

    dim3 g1(D_HID / 128, M_ROWS / 128);   // (16, 64)
    gemm3x_kernel<0><<<g1, 256, SMEM_BYTES>>>(x, b2, out);

    dim3 g2(KW / 128, M_ROWS / 128);      // (64, 64)
    gemm3x_kernel<1><<<g2, 256, SMEM_BYTES>>>(x, b2, out);
}

// round 5
// speedup vs baseline: 4.2581x; 1.4247x over previous
#include <cuda_runtime.h>
#include <cuda_fp16.h>
#include <cstdint>
#include <cstddef>

#define D_HID 2048
#define T_LEN 4096
#define M_ROWS 8192
#define KW 8192

// ---------------- scratch (static device arrays: allocation-guard safe) ----
__device__ __align__(256) __half g_xhi[(size_t)M_ROWS * D_HID];
__device__ __align__(256) __half g_xlo[(size_t)M_ROWS * D_HID];
__device__ __align__(256) __half g_w1h[(size_t)D_HID * D_HID];
__device__ __align__(256) __half g_w2h[(size_t)KW * D_HID];
__device__ __align__(256) __half g_hhi[(size_t)M_ROWS * D_HID];
__device__ __align__(256) __half g_hlo[(size_t)M_ROWS * D_HID];

// ---------------- helpers ---------------------------------------------------
__device__ __forceinline__ uint32_t smem_u32(const void* p) {
    uint32_t a;
    asm("{ .reg .u64 t; cvta.to.shared.u64 t, %1; cvt.u32.u64 %0, t; }"
        : "=r"(a) : "l"(p));
    return a;
}
__device__ __forceinline__ void cp16(uint32_t dst, const void* src) {
    asm volatile("cp.async.cg.shared.global [%0], [%1], 16;" :: "r"(dst), "l"(src));
}
#define CP_COMMIT() asm volatile("cp.async.commit_group;" ::: "memory")
#define CP_WAIT2()  asm volatile("cp.async.wait_group 2;" ::: "memory")

__device__ __forceinline__ void ldsm4(uint32_t r[4], uint32_t addr) {
    asm volatile("ldmatrix.sync.aligned.m8n8.x4.shared.b16 {%0,%1,%2,%3}, [%4];"
        : "=r"(r[0]), "=r"(r[1]), "=r"(r[2]), "=r"(r[3]) : "r"(addr));
}
__device__ __forceinline__ void mma_f16(float c[4], const uint32_t a[4],
                                        uint32_t b0, uint32_t b1) {
    asm volatile("mma.sync.aligned.m16n8k16.row.col.f32.f16.f16.f32 "
        "{%0,%1,%2,%3}, {%4,%5,%6,%7}, {%8,%9}, {%0,%1,%2,%3};"
        : "+f"(c[0]), "+f"(c[1]), "+f"(c[2]), "+f"(c[3])
        : "r"(a[0]), "r"(a[1]), "r"(a[2]), "r"(a[3]), "r"(b0), "r"(b1));
}
__device__ __forceinline__ float silu_f(float v) { return v / (1.0f + __expf(-v)); }

// swizzled byte offset within a [128 rows][32 cols f16] tile (64B rows)
__device__ __forceinline__ uint32_t sw_off(int row, int c16) {
    return (uint32_t)(row * 64 + ((c16 ^ ((row >> 1) & 3)) << 4));
}

// ---------------- split / round: fp32 -> fp16 -------------------------------
__global__ void split2h_kernel(const float* __restrict__ in, __half* __restrict__ hi,
                               __half* __restrict__ lo, int n4) {
    int i = blockIdx.x * blockDim.x + threadIdx.x;
    if (i >= n4) return;
    float4 v = ((const float4*)in)[i];
    __half h0 = __float2half_rn(v.x), h1 = __float2half_rn(v.y);
    __half h2 = __float2half_rn(v.z), h3 = __float2half_rn(v.w);
    __half2 hp0 = __halves2half2(h0, h1), hp1 = __halves2half2(h2, h3);
    __half2 lp0 = __halves2half2(__float2half_rn(v.x - __half2float(h0)),
                                 __float2half_rn(v.y - __half2float(h1)));
    __half2 lp1 = __halves2half2(__float2half_rn(v.z - __half2float(h2)),
                                 __float2half_rn(v.w - __half2float(h3)));
    ((__half2*)hi)[2 * i] = hp0; ((__half2*)hi)[2 * i + 1] = hp1;
    ((__half2*)lo)[2 * i] = lp0; ((__half2*)lo)[2 * i + 1] = lp1;
}
__global__ void roundh_kernel(const float* __restrict__ in, __half* __restrict__ hi,
                              int n4) {
    int i = blockIdx.x * blockDim.x + threadIdx.x;
    if (i >= n4) return;
    float4 v = ((const float4*)in)[i];
    __half2 hp0 = __halves2half2(__float2half_rn(v.x), __float2half_rn(v.y));
    __half2 hp1 = __halves2half2(__float2half_rn(v.z), __float2half_rn(v.w));
    ((__half2*)hi)[2 * i] = hp0; ((__half2*)hi)[2 * i + 1] = hp1;
}

// ---------------- main mma.sync GEMM (2-pass FP16) --------------------------
// stage layout: Ahi[128][32] +0, Alo +8192, Bh +16384  (24 KB / stage, 4 stages)
#define STAGE_B 24576u
#define SMEM_BYTES (4 * 24576)   // 98304; epilogue reuses this region

template<int MODE>
__global__ void __launch_bounds__(256, 2)
gemm2p_kernel(const float* __restrict__ xin, const float* __restrict__ b2,
              float* __restrict__ out) {
    extern __shared__ char smem[];
    uint32_t sb = smem_u32(smem);
    const int tid = threadIdx.x;
    const int l   = tid & 31;
    const int wid = tid >> 5;
    const int wm  = wid & 1;    // 2 M-warps (64 rows each)
    const int wn  = wid >> 1;   // 4 N-warps (32 cols each)
    const int bm = blockIdx.y * 128, bn = blockIdx.x * 128;

    const __half* Ahi = (MODE == 0 ? g_xhi : g_hhi) + (size_t)bm * D_HID;
    const __half* Alo = (MODE == 0 ? g_xlo : g_hlo) + (size_t)bm * D_HID;
    const __half* Bh  = (MODE == 0 ? g_w1h : g_w2h) + (size_t)bn * D_HID;

    // ---- hoisted cp.async addressing: 2 rows per tile per thread ----
    const int lrow = tid >> 2, lc16 = tid & 3;
    const uint32_t so0 = sw_off(lrow, lc16);   // slot0; slot1 = +4096 (row+64)
    const __half* srcA0 = Ahi + (size_t)lrow * D_HID + lc16 * 8;
    const __half* srcA1 = Alo + (size_t)lrow * D_HID + lc16 * 8;
    const __half* srcB0 = Bh  + (size_t)lrow * D_HID + lc16 * 8;
    const size_t R64 = (size_t)64 * D_HID;

    // ---- hoisted ldmatrix offsets (tile-relative) ----
    uint32_t offA[4][2], offB[2][2];
    #pragma unroll
    for (int mt = 0; mt < 4; mt++) {
        int row = wm * 64 + mt * 16 + (l & 15);
        #pragma unroll
        for (int ks = 0; ks < 2; ks++)
            offA[mt][ks] = sw_off(row, ks * 2 + (l >> 4));
    }
    #pragma unroll
    for (int blk = 0; blk < 2; blk++) {
        int row = wn * 32 + blk * 16 + (l & 15);
        #pragma unroll
        for (int ks = 0; ks < 2; ks++)
            offB[blk][ks] = sw_off(row, ks * 2 + (l >> 4));
    }

    float acc[4][4][4];
    #pragma unroll
    for (int a = 0; a < 4; a++)
        #pragma unroll
        for (int b = 0; b < 4; b++)
            #pragma unroll
            for (int c = 0; c < 4; c++) acc[a][b][c] = 0.f;

    uint32_t sb0 = sb, sb1 = sb + STAGE_B, sb2 = sb + 2 * STAGE_B,
             sb3 = sb + 3 * STAGE_B;

    // one stage load = 6 cp16 per thread (3 tiles x 2 row-slots)
    #define DO_LOAD(base) do { \
        uint32_t _t = (base) + so0; \
        cp16(_t,             srcA0); cp16(_t + 4096,         srcA0 + R64); \
        cp16(_t + 8192,      srcA1); cp16(_t + 8192 + 4096,  srcA1 + R64); \
        cp16(_t + 16384,     srcB0); cp16(_t + 16384 + 4096, srcB0 + R64); \
        srcA0 += 32; srcA1 += 32; srcB0 += 32; \
    } while (0)

    DO_LOAD(sb0); CP_COMMIT();
    DO_LOAD(sb1); CP_COMMIT();
    DO_LOAD(sb2); CP_COMMIT();

    const int NIT = D_HID / 32;   // 64
    for (int it = 0; it < NIT; it++) {
        CP_WAIT2();
        __syncthreads();
        // prefetch stage it+3 into the buffer consumed at it-1
        if (it < NIT - 3) DO_LOAD(sb3);
        CP_COMMIT();

        #pragma unroll
        for (int ks = 0; ks < 2; ks++) {
            uint32_t bh[2][4];
            ldsm4(bh[0], sb0 + 16384u + offB[0][ks]);
            ldsm4(bh[1], sb0 + 16384u + offB[1][ks]);
            #pragma unroll
            for (int mt = 0; mt < 4; mt++) {
                uint32_t ah[4], al[4];
                ldsm4(ah, sb0 + offA[mt][ks]);
                ldsm4(al, sb0 + 8192u + offA[mt][ks]);
                #pragma unroll
                for (int blk = 0; blk < 2; blk++) {
                    #pragma unroll
                    for (int sub = 0; sub < 2; sub++) {
                        float* C = acc[mt][blk * 2 + sub];
                        mma_f16(C, ah, bh[blk][sub], bh[blk][sub + 2]);
                        mma_f16(C, al, bh[blk][sub], bh[blk][sub + 2]);
                    }
                }
            }
        }
        // rotate stages
        uint32_t t = sb0; sb0 = sb1; sb1 = sb2; sb2 = sb3; sb3 = t;
    }
    __syncthreads();   // pipeline smem now reusable for epilogue

    if (MODE == 0) {
        // silu + fp16 split of h, staged for coalesced global stores
        uint32_t* hi_buf = (uint32_t*)smem;            // [128][66]
        uint32_t* lo_buf = hi_buf + 128 * 66;
        #pragma unroll
        for (int mt = 0; mt < 4; mt++) {
            #pragma unroll
            for (int nt = 0; nt < 4; nt++) {
                int r0 = wm * 64 + mt * 16 + (l >> 2);
                int cu = wn * 16 + nt * 4 + (l & 3);
                #pragma unroll
                for (int half = 0; half < 2; half++) {
                    int r = r0 + half * 8;
                    float v0 = silu_f(acc[mt][nt][half * 2 + 0]);
                    float v1 = silu_f(acc[mt][nt][half * 2 + 1]);
                    __half h0 = __float2half_rn(v0), h1 = __float2half_rn(v1);
                    __half2 hp = __halves2half2(h0, h1);
                    __half2 lp = __halves2half2(
                        __float2half_rn(v0 - __half2float(h0)),
                        __float2half_rn(v1 - __half2float(h1)));
                    hi_buf[r * 66 + cu] = *(uint32_t*)&hp;
                    lo_buf[r * 66 + cu] = *(uint32_t*)&lp;
                }
            }
        }
        __syncthreads();
        for (int idx = tid; idx < 128 * 64; idx += 256) {
            int r = idx >> 6, c = idx & 63;
            ((uint32_t*)(g_hhi + (size_t)(bm + r) * D_HID + bn))[c] = hi_buf[r * 66 + c];
            ((uint32_t*)(g_hlo + (size_t)(bm + r) * D_HID + bn))[c] = lo_buf[r * 66 + c];
        }
    } else {
        // bias + causal 4-tap dynamic conv + silu
        float* ksm = (float*)smem;                  // [4][128][33]
        float* xs  = (float*)(smem + 67584);        // [131][33]
        float* b2s = (float*)(smem + 67584 + 17292 + 4);  // [128]
        const int b  = bm >> 12;
        const int t0 = bm & (T_LEN - 1);
        const int d0 = bn >> 2;
        for (int idx = tid; idx < 131 * 32; idx += 256) {
            int r = idx >> 5, c = idx & 31;
            int t = t0 - 3 + r;
            float v = 0.f;
            if (t >= 0) v = xin[((size_t)b * T_LEN + t) * D_HID + d0 + c];
            xs[r * 33 + c] = v;
        }
        if (tid < 128) b2s[tid] = b2[bn + tid];
        __syncthreads();
        #pragma unroll
        for (int mt = 0; mt < 4; mt++) {
            #pragma unroll
            for (int nt = 0; nt < 4; nt++) {
                int r0   = wm * 64 + mt * 16 + (l >> 2);
                int col0 = wn * 32 + nt * 8 + (l & 3) * 2;
                #pragma unroll
                for (int cc = 0; cc < 4; cc++) {
                    int r   = r0 + ((cc >> 1) << 3);
                    int col = col0 + (cc & 1);
                    float val = acc[mt][nt][cc] + b2s[col];
                    ksm[(((col & 3) * 128) + r) * 33 + (col >> 2)] = val;
                }
            }
        }
        __syncthreads();
        {
            int c = tid & 31, rg = tid >> 5;
            #pragma unroll
            for (int i = 0; i < 16; i++) {
                int r = rg * 16 + i;
                float y = 0.f;
                #pragma unroll
                for (int w = 0; w < 4; w++)
                    y += xs[(r + w) * 33 + c] * ksm[((w * 128) + r) * 33 + c];
                out[(size_t)(bm + r) * D_HID + d0 + c] = silu_f(y);
            }
        }
    }
}

// ---------------- launch ----------------------------------------------------
extern "C" void kernel_launch(void* const* d_in, const int* in_sizes, int n_in,
                              void* d_out, int out_size) {
    const float* x  = (const float*)d_in[0];   // [2,4096,2048]
    const float* w1 = (const float*)d_in[1];   // [2048,2048]
    const float* w2 = (const float*)d_in[2];   // [8192,2048]
    const float* b2 = (const float*)d_in[3];   // [8192]
    float* out = (float*)d_out;

    cudaFuncSetAttribute(gemm2p_kernel<0>, cudaFuncAttributeMaxDynamicSharedMemorySize, SMEM_BYTES);
    cudaFuncSetAttribute(gemm2p_kernel<1>, cudaFuncAttributeMaxDynamicSharedMemorySize, SMEM_BYTES);

    void *pxh, *pxl, *pw1, *pw2;
    cudaGetSymbolAddress(&pxh, g_xhi); cudaGetSymbolAddress(&pxl, g_xlo);
    cudaGetSymbolAddress(&pw1, g_w1h); cudaGetSymbolAddress(&pw2, g_w2h);

    {
        int n4 = M_ROWS * D_HID / 4;
        split2h_kernel<<<(n4 + 255) / 256, 256>>>(x, (__half*)pxh, (__half*)pxl, n4);
    }
    {
        int n4 = D_HID * D_HID / 4;
        roundh_kernel<<<(n4 + 255) / 256, 256>>>(w1, (__half*)pw1, n4);
    }
    {
        int n4 = KW * D_HID / 4;
        roundh_kernel<<<(n4 + 255) / 256, 256>>>(w2, (__half*)pw2, n4);
    }

    dim3 g1(D_HID / 128, M_ROWS / 128);   // (16, 64)
    gemm2p_kernel<0><<<g1, 256, SMEM_BYTES>>>(x, b2, out);

    dim3 g2(KW / 128, M_ROWS / 128);      // (64, 64)
    gemm2p_kernel<1><<<g2, 256, SMEM_BYTES>>>(x, b2, out);
}

// round 6
// speedup vs baseline: 7.3488x; 1.7259x over previous
#include <cuda_runtime.h>
#include <cuda_fp16.h>
#include <cstdint>
#include <cstddef>

#define D_HID 2048
#define T_LEN 4096
#define M_ROWS 8192
#define KW 8192

// ---------------- scratch (static device arrays: allocation-guard safe) ----
__device__ __align__(256) __half g_xh[(size_t)M_ROWS * D_HID];
__device__ __align__(256) __half g_w1h[(size_t)D_HID * D_HID];
__device__ __align__(256) __half g_w2h[(size_t)KW * D_HID];
__device__ __align__(256) __half g_hh[(size_t)M_ROWS * D_HID];

// ---------------- helpers ---------------------------------------------------
__device__ __forceinline__ uint32_t smem_u32(const void* p) {
    uint32_t a;
    asm("{ .reg .u64 t; cvta.to.shared.u64 t, %1; cvt.u32.u64 %0, t; }"
        : "=r"(a) : "l"(p));
    return a;
}
__device__ __forceinline__ void cp16(uint32_t dst, const void* src) {
    asm volatile("cp.async.cg.shared.global [%0], [%1], 16;" :: "r"(dst), "l"(src));
}
#define CP_COMMIT() asm volatile("cp.async.commit_group;" ::: "memory")
#define CP_WAIT1()  asm volatile("cp.async.wait_group 1;" ::: "memory")

__device__ __forceinline__ void ldsm4(uint32_t r[4], uint32_t addr) {
    asm volatile("ldmatrix.sync.aligned.m8n8.x4.shared.b16 {%0,%1,%2,%3}, [%4];"
        : "=r"(r[0]), "=r"(r[1]), "=r"(r[2]), "=r"(r[3]) : "r"(addr));
}
__device__ __forceinline__ void mma_f16(float c[4], const uint32_t a[4],
                                        uint32_t b0, uint32_t b1) {
    asm volatile("mma.sync.aligned.m16n8k16.row.col.f32.f16.f16.f32 "
        "{%0,%1,%2,%3}, {%4,%5,%6,%7}, {%8,%9}, {%0,%1,%2,%3};"
        : "+f"(c[0]), "+f"(c[1]), "+f"(c[2]), "+f"(c[3])
        : "r"(a[0]), "r"(a[1]), "r"(a[2]), "r"(a[3]), "r"(b0), "r"(b1));
}
__device__ __forceinline__ float silu_f(float v) { return v / (1.0f + __expf(-v)); }

// swizzled byte offset within a [128 rows][32 cols f16] tile (64B rows)
__device__ __forceinline__ uint32_t sw_off(int row, int c16) {
    return (uint32_t)(row * 64 + ((c16 ^ ((row >> 1) & 3)) << 4));
}

// ---------------- round: fp32 -> fp16 ---------------------------------------
__global__ void roundh_kernel(const float* __restrict__ in, __half* __restrict__ hi,
                              int n4) {
    int i = blockIdx.x * blockDim.x + threadIdx.x;
    if (i >= n4) return;
    float4 v = ((const float4*)in)[i];
    __half2 hp0 = __halves2half2(__float2half_rn(v.x), __float2half_rn(v.y));
    __half2 hp1 = __halves2half2(__float2half_rn(v.z), __float2half_rn(v.w));
    ((__half2*)hi)[2 * i] = hp0; ((__half2*)hi)[2 * i + 1] = hp1;
}

// ---------------- main mma.sync GEMM (single-pass FP16, BK=64) --------------
// stage: A_t0[128][32] +0, A_t1 +8192, B_t0 +16384, B_t1 +24576 (32 KB/stage)
#define STAGE_B 32768u
#define SMEM_BYTES (3 * 32768)   // 98304; epilogue reuses this region

template<int MODE>
__global__ void __launch_bounds__(256, 2)
gemm1p_kernel(const float* __restrict__ xin, const float* __restrict__ b2,
              float* __restrict__ out) {
    extern __shared__ char smem[];
    uint32_t sb = smem_u32(smem);
    const int tid = threadIdx.x;
    const int l   = tid & 31;
    const int wid = tid >> 5;
    const int wm  = wid & 1;    // 2 M-warps (64 rows each)
    const int wn  = wid >> 1;   // 4 N-warps (32 cols each)
    const int bm = blockIdx.y * 128, bn = blockIdx.x * 128;

    const __half* Ah = (MODE == 0 ? g_xh : g_hh) + (size_t)bm * D_HID;
    const __half* Bh = (MODE == 0 ? g_w1h : g_w2h) + (size_t)bn * D_HID;

    // ---- hoisted cp.async addressing ----
    const int lrow = tid >> 2, lc16 = tid & 3;
    const uint32_t so0 = sw_off(lrow, lc16);   // slot0; row+64 slot = +4096
    const __half* srcA = Ah + (size_t)lrow * D_HID + lc16 * 8;
    const __half* srcB = Bh + (size_t)lrow * D_HID + lc16 * 8;
    const size_t R64 = (size_t)64 * D_HID;

    // ---- hoisted ldmatrix offsets (tile-relative, for the 2 k16 of a tile) ----
    uint32_t offA[4][2], offB[2][2];
    #pragma unroll
    for (int mt = 0; mt < 4; mt++) {
        int row = wm * 64 + mt * 16 + (l & 15);
        #pragma unroll
        for (int ks = 0; ks < 2; ks++)
            offA[mt][ks] = sw_off(row, ks * 2 + (l >> 4));
    }
    #pragma unroll
    for (int blk = 0; blk < 2; blk++) {
        int row = wn * 32 + blk * 16 + (l & 15);
        #pragma unroll
        for (int ks = 0; ks < 2; ks++)
            offB[blk][ks] = sw_off(row, ks * 2 + (l >> 4));
    }

    float acc[4][4][4];
    #pragma unroll
    for (int a = 0; a < 4; a++)
        #pragma unroll
        for (int b = 0; b < 4; b++)
            #pragma unroll
            for (int c = 0; c < 4; c++) acc[a][b][c] = 0.f;

    uint32_t sb0 = sb, sb1 = sb + STAGE_B, sb2 = sb + 2 * STAGE_B;

    // one stage (BK=64) = 8 cp16 per thread: {A,B} x {ktile0,ktile1} x {row,row+64}
    #define DO_LOAD(base) do { \
        uint32_t _t = (base) + so0; \
        cp16(_t,              srcA);       cp16(_t + 4096,          srcA + R64); \
        cp16(_t + 8192,       srcA + 32);  cp16(_t + 8192 + 4096,   srcA + R64 + 32); \
        cp16(_t + 16384,      srcB);       cp16(_t + 16384 + 4096,  srcB + R64); \
        cp16(_t + 24576,      srcB + 32);  cp16(_t + 24576 + 4096,  srcB + R64 + 32); \
        srcA += 64; srcB += 64; \
    } while (0)

    DO_LOAD(sb0); CP_COMMIT();
    DO_LOAD(sb1); CP_COMMIT();

    const int NIT = D_HID / 64;   // 32
    for (int it = 0; it < NIT; it++) {
        CP_WAIT1();
        __syncthreads();
        // prefetch stage it+2 into the buffer consumed at it-1
        if (it < NIT - 2) DO_LOAD(sb2);
        CP_COMMIT();

        #pragma unroll
        for (int kt = 0; kt < 2; kt++) {
            uint32_t abase = sb0 + (uint32_t)kt * 8192u;
            uint32_t bbase = sb0 + 16384u + (uint32_t)kt * 8192u;
            #pragma unroll
            for (int ks = 0; ks < 2; ks++) {
                uint32_t bh[2][4];
                ldsm4(bh[0], bbase + offB[0][ks]);
                ldsm4(bh[1], bbase + offB[1][ks]);
                #pragma unroll
                for (int mt = 0; mt < 4; mt++) {
                    uint32_t ah[4];
                    ldsm4(ah, abase + offA[mt][ks]);
                    #pragma unroll
                    for (int blk = 0; blk < 2; blk++) {
                        #pragma unroll
                        for (int sub = 0; sub < 2; sub++) {
                            mma_f16(acc[mt][blk * 2 + sub], ah,
                                    bh[blk][sub], bh[blk][sub + 2]);
                        }
                    }
                }
            }
        }
        // rotate stages
        uint32_t t = sb0; sb0 = sb1; sb1 = sb2; sb2 = t;
    }
    __syncthreads();   // pipeline smem now reusable for epilogue

    if (MODE == 0) {
        // silu + round to fp16, staged for coalesced global stores
        uint32_t* h_buf = (uint32_t*)smem;            // [128][66]
        #pragma unroll
        for (int mt = 0; mt < 4; mt++) {
            #pragma unroll
            for (int nt = 0; nt < 4; nt++) {
                int r0 = wm * 64 + mt * 16 + (l >> 2);
                int cu = wn * 16 + nt * 4 + (l & 3);
                #pragma unroll
                for (int half = 0; half < 2; half++) {
                    int r = r0 + half * 8;
                    float v0 = silu_f(acc[mt][nt][half * 2 + 0]);
                    float v1 = silu_f(acc[mt][nt][half * 2 + 1]);
                    __half2 hp = __halves2half2(__float2half_rn(v0),
                                                __float2half_rn(v1));
                    h_buf[r * 66 + cu] = *(uint32_t*)&hp;
                }
            }
        }
        __syncthreads();
        for (int idx = tid; idx < 128 * 64; idx += 256) {
            int r = idx >> 6, c = idx & 63;
            ((uint32_t*)(g_hh + (size_t)(bm + r) * D_HID + bn))[c] = h_buf[r * 66 + c];
        }
    } else {
        // bias + causal 4-tap dynamic conv + silu
        float* ksm = (float*)smem;                  // [4][128][33]
        float* xs  = (float*)(smem + 67584);        // [131][33]
        float* b2s = (float*)(smem + 67584 + 17292 + 4);  // [128]
        const int b  = bm >> 12;
        const int t0 = bm & (T_LEN - 1);
        const int d0 = bn >> 2;
        for (int idx = tid; idx < 131 * 32; idx += 256) {
            int r = idx >> 5, c = idx & 31;
            int t = t0 - 3 + r;
            float v = 0.f;
            if (t >= 0) v = xin[((size_t)b * T_LEN + t) * D_HID + d0 + c];
            xs[r * 33 + c] = v;
        }
        if (tid < 128) b2s[tid] = b2[bn + tid];
        __syncthreads();
        #pragma unroll
        for (int mt = 0; mt < 4; mt++) {
            #pragma unroll
            for (int nt = 0; nt < 4; nt++) {
                int r0   = wm * 64 + mt * 16 + (l >> 2);
                int col0 = wn * 32 + nt * 8 + (l & 3) * 2;
                #pragma unroll
                for (int cc = 0; cc < 4; cc++) {
                    int r   = r0 + ((cc >> 1) << 3);
                    int col = col0 + (cc & 1);
                    float val = acc[mt][nt][cc] + b2s[col];
                    ksm[(((col & 3) * 128) + r) * 33 + (col >> 2)] = val;
                }
            }
        }
        __syncthreads();
        {
            int c = tid & 31, rg = tid >> 5;
            #pragma unroll
            for (int i = 0; i < 16; i++) {
                int r = rg * 16 + i;
                float y = 0.f;
                #pragma unroll
                for (int w = 0; w < 4; w++)
                    y += xs[(r + w) * 33 + c] * ksm[((w * 128) + r) * 33 + c];
                out[(size_t)(bm + r) * D_HID + d0 + c] = silu_f(y);
            }
        }
    }
}

// ---------------- launch ----------------------------------------------------
extern "C" void kernel_launch(void* const* d_in, const int* in_sizes, int n_in,
                              void* d_out, int out_size) {
    const float* x  = (const float*)d_in[0];   // [2,4096,2048]
    const float* w1 = (const float*)d_in[1];   // [2048,2048]
    const float* w2 = (const float*)d_in[2];   // [8192,2048]
    const float* b2 = (const float*)d_in[3];   // [8192]
    float* out = (float*)d_out;

    cudaFuncSetAttribute(gemm1p_kernel<0>, cudaFuncAttributeMaxDynamicSharedMemorySize, SMEM_BYTES);
    cudaFuncSetAttribute(gemm1p_kernel<1>, cudaFuncAttributeMaxDynamicSharedMemorySize, SMEM_BYTES);

    void *pxh, *pw1, *pw2;
    cudaGetSymbolAddress(&pxh, g_xh);
    cudaGetSymbolAddress(&pw1, g_w1h);
    cudaGetSymbolAddress(&pw2, g_w2h);

    {
        int n4 = M_ROWS * D_HID / 4;
        roundh_kernel<<<(n4 + 255) / 256, 256>>>(x, (__half*)pxh, n4);
    }
    {
        int n4 = D_HID * D_HID / 4;
        roundh_kernel<<<(n4 + 255) / 256, 256>>>(w1, (__half*)pw1, n4);
    }
    {
        int n4 = KW * D_HID / 4;
        roundh_kernel<<<(n4 + 255) / 256, 256>>>(w2, (__half*)pw2, n4);
    }

    dim3 g1(D_HID / 128, M_ROWS / 128);   // (16, 64)
    gemm1p_kernel<0><<<g1, 256, SMEM_BYTES>>>(x, b2, out);

    dim3 g2(KW / 128, M_ROWS / 128);      // (64, 64)
    gemm1p_kernel<1><<<g2, 256, SMEM_BYTES>>>(x, b2, out);
}

// round 7
// speedup vs baseline: 7.6139x; 1.0361x over previous
#include <cuda_runtime.h>
#include <cuda_fp16.h>
#include <cstdint>
#include <cstddef>

#define D_HID 2048
#define T_LEN 4096
#define M_ROWS 8192
#define KW 8192

// ---------------- scratch (static device arrays: allocation-guard safe) ----
__device__ __align__(256) __half g_xh[(size_t)M_ROWS * D_HID];
__device__ __align__(256) __half g_w1h[(size_t)D_HID * D_HID];
__device__ __align__(256) __half g_w2h[(size_t)KW * D_HID];
__device__ __align__(256) __half g_hh[(size_t)M_ROWS * D_HID];

// ---------------- helpers ---------------------------------------------------
__device__ __forceinline__ uint32_t smem_u32(const void* p) {
    uint32_t a;
    asm("{ .reg .u64 t; cvta.to.shared.u64 t, %1; cvt.u32.u64 %0, t; }"
        : "=r"(a) : "l"(p));
    return a;
}
__device__ __forceinline__ void cp16(uint32_t dst, const void* src) {
    asm volatile("cp.async.cg.shared.global [%0], [%1], 16;" :: "r"(dst), "l"(src));
}
#define CP_COMMIT() asm volatile("cp.async.commit_group;" ::: "memory")
#define CP_WAIT1()  asm volatile("cp.async.wait_group 1;" ::: "memory")

__device__ __forceinline__ void ldsm4(uint32_t r[4], uint32_t addr) {
    asm volatile("ldmatrix.sync.aligned.m8n8.x4.shared.b16 {%0,%1,%2,%3}, [%4];"
        : "=r"(r[0]), "=r"(r[1]), "=r"(r[2]), "=r"(r[3]) : "r"(addr));
}
__device__ __forceinline__ void mma_f16(float c[4], const uint32_t a[4],
                                        uint32_t b0, uint32_t b1) {
    asm volatile("mma.sync.aligned.m16n8k16.row.col.f32.f16.f16.f32 "
        "{%0,%1,%2,%3}, {%4,%5,%6,%7}, {%8,%9}, {%0,%1,%2,%3};"
        : "+f"(c[0]), "+f"(c[1]), "+f"(c[2]), "+f"(c[3])
        : "r"(a[0]), "r"(a[1]), "r"(a[2]), "r"(a[3]), "r"(b0), "r"(b1));
}
__device__ __forceinline__ float silu_f(float v) { return v / (1.0f + __expf(-v)); }

// swizzled byte offset within a [rows][32 cols f16] tile (64B rows)
__device__ __forceinline__ uint32_t sw_off(int row, int c16) {
    return (uint32_t)(row * 64 + ((c16 ^ ((row >> 1) & 3)) << 4));
}

// ---------------- round: fp32 -> fp16 ---------------------------------------
__global__ void roundh_kernel(const float* __restrict__ in, __half* __restrict__ hi,
                              int n4) {
    int i = blockIdx.x * blockDim.x + threadIdx.x;
    if (i >= n4) return;
    float4 v = ((const float4*)in)[i];
    __half2 hp0 = __halves2half2(__float2half_rn(v.x), __float2half_rn(v.y));
    __half2 hp1 = __halves2half2(__float2half_rn(v.z), __float2half_rn(v.w));
    ((__half2*)hi)[2 * i] = hp0; ((__half2*)hi)[2 * i + 1] = hp1;
}

// ---------------- main mma.sync GEMM (1-pass FP16, CTA 64x128, BK=64) -------
// stage: A_t0[64][32] @0 (4KB), A_t1 @4096, B_t0[128][32] @8192 (8KB),
//        B_t1 @16384 (8KB) -> 24 KB/stage, 3 stages
#define STAGE_B 24576u
#define SMEM_BYTES (3 * 24576)   // 73728; epilogue reuses this region

template<int MODE>
__global__ void __launch_bounds__(256, 3)
gemm1p_kernel(const float* __restrict__ xin, const float* __restrict__ b2,
              float* __restrict__ out) {
    extern __shared__ char smem[];
    uint32_t sb = smem_u32(smem);
    const int tid = threadIdx.x;
    const int l   = tid & 31;
    const int wid = tid >> 5;
    const int wm  = wid & 1;    // 2 M-warps (32 rows each)
    const int wn  = wid >> 1;   // 4 N-warps (32 cols each)
    const int bm = blockIdx.y * 64, bn = blockIdx.x * 128;

    const __half* Ah = (MODE == 0 ? g_xh : g_hh) + (size_t)bm * D_HID;
    const __half* Bh = (MODE == 0 ? g_w1h : g_w2h) + (size_t)bn * D_HID;

    // ---- hoisted cp.async addressing ----
    const int lrow = tid >> 2, lc16 = tid & 3;   // lrow 0..63
    const uint32_t so = sw_off(lrow, lc16);      // B row+64 slot = +4096
    const __half* srcA = Ah + (size_t)lrow * D_HID + lc16 * 8;
    const __half* srcB = Bh + (size_t)lrow * D_HID + lc16 * 8;
    const size_t R64 = (size_t)64 * D_HID;

    // ---- hoisted ldmatrix offsets (tile-relative) ----
    uint32_t offA[2][2], offB[2][2];
    #pragma unroll
    for (int mt = 0; mt < 2; mt++) {
        int row = wm * 32 + mt * 16 + (l & 15);
        #pragma unroll
        for (int ks = 0; ks < 2; ks++)
            offA[mt][ks] = sw_off(row, ks * 2 + (l >> 4));
    }
    #pragma unroll
    for (int blk = 0; blk < 2; blk++) {
        int row = wn * 32 + blk * 16 + (l & 15);
        #pragma unroll
        for (int ks = 0; ks < 2; ks++)
            offB[blk][ks] = sw_off(row, ks * 2 + (l >> 4));
    }

    float acc[2][4][4];
    #pragma unroll
    for (int a = 0; a < 2; a++)
        #pragma unroll
        for (int b = 0; b < 4; b++)
            #pragma unroll
            for (int c = 0; c < 4; c++) acc[a][b][c] = 0.f;

    uint32_t sb0 = sb, sb1 = sb + STAGE_B, sb2 = sb + 2 * STAGE_B;

    // one stage = 6 cp16 per thread
    #define DO_LOAD(base) do { \
        uint32_t _t = (base) + so; \
        cp16(_t,                 srcA);        cp16(_t + 4096,          srcA + 32); \
        cp16(_t + 8192,          srcB);        cp16(_t + 8192 + 4096,   srcB + R64); \
        cp16(_t + 16384,         srcB + 32);   cp16(_t + 16384 + 4096,  srcB + R64 + 32); \
        srcA += 64; srcB += 64; \
    } while (0)

    DO_LOAD(sb0); CP_COMMIT();
    DO_LOAD(sb1); CP_COMMIT();

    const int NIT = D_HID / 64;   // 32
    for (int it = 0; it < NIT; it++) {
        CP_WAIT1();
        __syncthreads();
        if (it < NIT - 2) DO_LOAD(sb2);
        CP_COMMIT();

        #pragma unroll
        for (int kt = 0; kt < 2; kt++) {
            uint32_t abase = sb0 + (uint32_t)kt * 4096u;
            uint32_t bbase = sb0 + 8192u + (uint32_t)kt * 8192u;
            #pragma unroll
            for (int ks = 0; ks < 2; ks++) {
                uint32_t bh[2][4];
                ldsm4(bh[0], bbase + offB[0][ks]);
                ldsm4(bh[1], bbase + offB[1][ks]);
                #pragma unroll
                for (int mt = 0; mt < 2; mt++) {
                    uint32_t ah[4];
                    ldsm4(ah, abase + offA[mt][ks]);
                    #pragma unroll
                    for (int blk = 0; blk < 2; blk++) {
                        #pragma unroll
                        for (int sub = 0; sub < 2; sub++) {
                            mma_f16(acc[mt][blk * 2 + sub], ah,
                                    bh[blk][sub], bh[blk][sub + 2]);
                        }
                    }
                }
            }
        }
        uint32_t t = sb0; sb0 = sb1; sb1 = sb2; sb2 = t;
    }
    __syncthreads();   // pipeline smem now reusable for epilogue

    if (MODE == 0) {
        // silu + round to fp16, staged for coalesced global stores
        uint32_t* h_buf = (uint32_t*)smem;            // [64][66]
        #pragma unroll
        for (int mt = 0; mt < 2; mt++) {
            #pragma unroll
            for (int nt = 0; nt < 4; nt++) {
                int r0 = wm * 32 + mt * 16 + (l >> 2);
                int cu = wn * 16 + nt * 4 + (l & 3);
                #pragma unroll
                for (int half = 0; half < 2; half++) {
                    int r = r0 + half * 8;
                    float v0 = silu_f(acc[mt][nt][half * 2 + 0]);
                    float v1 = silu_f(acc[mt][nt][half * 2 + 1]);
                    __half2 hp = __halves2half2(__float2half_rn(v0),
                                                __float2half_rn(v1));
                    h_buf[r * 66 + cu] = *(uint32_t*)&hp;
                }
            }
        }
        __syncthreads();
        for (int idx = tid; idx < 64 * 64; idx += 256) {
            int r = idx >> 6, c = idx & 63;
            ((uint32_t*)(g_hh + (size_t)(bm + r) * D_HID + bn))[c] = h_buf[r * 66 + c];
        }
    } else {
        // bias + causal 4-tap dynamic conv + silu
        float* ksm = (float*)smem;                  // [4][64][33]  = 33792 B
        float* xs  = (float*)(smem + 33792);        // [67][33]     =  8844 B
        float* b2s = (float*)(smem + 33792 + 8844 + 4);  // [128]
        const int b  = bm >> 12;
        const int t0 = bm & (T_LEN - 1);
        const int d0 = bn >> 2;
        for (int idx = tid; idx < 67 * 32; idx += 256) {
            int r = idx >> 5, c = idx & 31;
            int t = t0 - 3 + r;
            float v = 0.f;
            if (t >= 0) v = xin[((size_t)b * T_LEN + t) * D_HID + d0 + c];
            xs[r * 33 + c] = v;
        }
        if (tid < 128) b2s[tid] = b2[bn + tid];
        __syncthreads();
        #pragma unroll
        for (int mt = 0; mt < 2; mt++) {
            #pragma unroll
            for (int nt = 0; nt < 4; nt++) {
                int r0   = wm * 32 + mt * 16 + (l >> 2);
                int col0 = wn * 32 + nt * 8 + (l & 3) * 2;
                #pragma unroll
                for (int cc = 0; cc < 4; cc++) {
                    int r   = r0 + ((cc >> 1) << 3);
                    int col = col0 + (cc & 1);
                    float val = acc[mt][nt][cc] + b2s[col];
                    ksm[(((col & 3) * 64) + r) * 33 + (col >> 2)] = val;
                }
            }
        }
        __syncthreads();
        {
            int c = tid & 31, rg = tid >> 5;   // rg 0..7, 8 rows each
            #pragma unroll
            for (int i = 0; i < 8; i++) {
                int r = rg * 8 + i;
                float y = 0.f;
                #pragma unroll
                for (int w = 0; w < 4; w++)
                    y += xs[(r + w) * 33 + c] * ksm[((w * 64) + r) * 33 + c];
                out[(size_t)(bm + r) * D_HID + d0 + c] = silu_f(y);
            }
        }
    }
}

// ---------------- launch ----------------------------------------------------
extern "C" void kernel_launch(void* const* d_in, const int* in_sizes, int n_in,
                              void* d_out, int out_size) {
    const float* x  = (const float*)d_in[0];   // [2,4096,2048]
    const float* w1 = (const float*)d_in[1];   // [2048,2048]
    const float* w2 = (const float*)d_in[2];   // [8192,2048]
    const float* b2 = (const float*)d_in[3];   // [8192]
    float* out = (float*)d_out;

    cudaFuncSetAttribute(gemm1p_kernel<0>, cudaFuncAttributeMaxDynamicSharedMemorySize, SMEM_BYTES);
    cudaFuncSetAttribute(gemm1p_kernel<1>, cudaFuncAttributeMaxDynamicSharedMemorySize, SMEM_BYTES);

    void *pxh, *pw1, *pw2;
    cudaGetSymbolAddress(&pxh, g_xh);
    cudaGetSymbolAddress(&pw1, g_w1h);
    cudaGetSymbolAddress(&pw2, g_w2h);

    {
        int n4 = M_ROWS * D_HID / 4;
        roundh_kernel<<<(n4 + 255) / 256, 256>>>(x, (__half*)pxh, n4);
    }
    {
        int n4 = D_HID * D_HID / 4;
        roundh_kernel<<<(n4 + 255) / 256, 256>>>(w1, (__half*)pw1, n4);
    }
    {
        int n4 = KW * D_HID / 4;
        roundh_kernel<<<(n4 + 255) / 256, 256>>>(w2, (__half*)pw2, n4);
    }

    dim3 g1(D_HID / 128, M_ROWS / 64);    // (16, 128)
    gemm1p_kernel<0><<<g1, 256, SMEM_BYTES>>>(x, b2, out);

    dim3 g2(KW / 128, M_ROWS / 64);       // (64, 128)
    gemm1p_kernel<1><<<g2, 256, SMEM_BYTES>>>(x, b2, out);
}